// round 1
// baseline (speedup 1.0000x reference)
#include <cuda_runtime.h>
#include <math.h>

// ---------------- problem constants ----------------
#define BSZ   16
#define A_N   32
#define G_N   512
#define S_N   4096
#define M_N   8
#define D_N   512
#define BS    (BSZ * S_N)      // 65536 rows
#define NGATE 1536
#define SPECT 512

// ---------------- scratch (device globals; no allocation allowed) ----------
__device__ float g_pref[5 * 20 * NGATE];      // thermometer prefix table
__device__ int   g_counts[BS * 5];
__device__ float g_bufA[(size_t)BS * G_N];    // 134 MB
__device__ float g_bufB[(size_t)BS * G_N];    // 134 MB
__device__ float g_gh[(size_t)BS * NGATE];    // 402 MB
__device__ float g_scores[BS];

// ---------------- kernel 0: prefix-sum W_ih columns per formula group ------
__global__ void k_prefix(const float* __restrict__ W_ih) {
    int o = blockIdx.x * blockDim.x + threadIdx.x;  // 0..1535
    if (o >= NGATE) return;
    #pragma unroll
    for (int g = 0; g < 5; g++) {
        float acc = 0.f;
        #pragma unroll
        for (int j = 0; j < 20; j++) {
            acc += W_ih[o * 100 + g * 20 + j];
            g_pref[(g * 20 + j) * NGATE + o] = acc;
        }
    }
}

// ---------------- kernel 1: swvs + counts + layernorm (normed -> g_bufA) ---
// grid (64, 16): 64 row-chunks of 64 rows x 16 batches. 256 threads (8 warps).
// Each warp owns one row at a time: lane = atom index.
__global__ __launch_bounds__(256) void k_pre(
    const float* __restrict__ vf, const float* __restrict__ mask,
    const float* __restrict__ eo, const float* __restrict__ subsets,
    const float* __restrict__ lng, const float* __restrict__ lnb)
{
    extern __shared__ float vfs[];                 // 32*512 floats = 64 KB
    __shared__ float s_lng[G_N], s_lnb[G_N];
    int b = blockIdx.y;
    int chunk = blockIdx.x;
    int tid = threadIdx.x;

    // masked vertex features for this batch into smem
    const float4* vf4 = (const float4*)(vf + (size_t)b * A_N * G_N);
    float4* vfs4 = (float4*)vfs;
    for (int i = tid; i < A_N * G_N / 4; i += 256) {
        float4 v = vf4[i];
        float m = mask[b * A_N + (i * 4) / G_N];
        v.x *= m; v.y *= m; v.z *= m; v.w *= m;
        vfs4[i] = v;
    }
    for (int i = tid; i < G_N; i += 256) { s_lng[i] = lng[i]; s_lnb[i] = lnb[i]; }
    __syncthreads();

    int warp = tid >> 5, lane = tid & 31;
    for (int it = 0; it < 8; it++) {
        int s = chunk * 64 + it * 8 + warp;
        int row = b * S_N + s;
        float as = subsets[(size_t)row * A_N + lane];
        float m  = mask[b * A_N + lane];
        float sm = as * m;

        // subset size (with mask)
        float ss = sm;
        #pragma unroll
        for (int o = 16; o; o >>= 1) ss += __shfl_xor_sync(0xffffffffu, ss, o);

        // element counts (uses UNmasked atom_subsets, per reference)
        #pragma unroll
        for (int e = 0; e < 5; e++) {
            float c = as * eo[(b * A_N + lane) * 5 + e];
            #pragma unroll
            for (int o = 16; o; o >>= 1) c += __shfl_xor_sync(0xffffffffu, c, o);
            if (lane == e) {
                int v = (int)c;
                v = v < 0 ? 0 : (v > 19 ? 19 : v);
                g_counts[row * 5 + e] = v;
            }
        }

        float inv_ss = 1.0f / (ss + 1e-4f);

        // swvs row: lane handles columns lane + 32*i
        float acc[16];
        #pragma unroll
        for (int i = 0; i < 16; i++) acc[i] = 0.f;
        #pragma unroll
        for (int a = 0; a < A_N; a++) {
            float sv = __shfl_sync(0xffffffffu, sm, a);
            #pragma unroll
            for (int i = 0; i < 16; i++)
                acc[i] += vfs[a * G_N + lane + 32 * i] * sv;
        }

        float sum = 0.f, sq = 0.f;
        #pragma unroll
        for (int i = 0; i < 16; i++) {
            acc[i] *= inv_ss;
            sum += acc[i];
            sq  += acc[i] * acc[i];
        }
        #pragma unroll
        for (int o = 16; o; o >>= 1) {
            sum += __shfl_xor_sync(0xffffffffu, sum, o);
            sq  += __shfl_xor_sync(0xffffffffu, sq,  o);
        }
        float mean = sum * (1.0f / G_N);
        float var  = sq  * (1.0f / G_N) - mean * mean;
        float inv  = rsqrtf(var + 1e-5f);
        #pragma unroll
        for (int i = 0; i < 16; i++) {
            int gc = lane + 32 * i;
            g_bufA[(size_t)row * G_N + gc] = (acc[i] - mean) * inv * s_lng[gc] + s_lnb[gc];
        }
    }
}

// ---------------- generic fp32 GEMM:  C = [relu](A[M,K] @ W[N,K]^T + bias) --
// BM=128 BN=64 BK=16, 256 threads, 8x4 micro-tile, register prefetch.
#define BM 128
#define BN 64
#define BK 16
template<bool RELU>
__global__ __launch_bounds__(256) void k_gemm(
    const float* __restrict__ A, const float* __restrict__ W,
    const float* __restrict__ bias, float* __restrict__ C,
    int M, int N, int K)
{
    __shared__ float As[BK][BM + 4];
    __shared__ float Bs[BK][BN + 4];
    int tid = threadIdx.x;
    int bm = blockIdx.y * BM;
    int bn = blockIdx.x * BN;
    int tx = tid & 15;          // N dim (x4)
    int ty = tid >> 4;          // M dim (x8)

    float acc[8][4];
    #pragma unroll
    for (int i = 0; i < 8; i++)
        #pragma unroll
        for (int j = 0; j < 4; j++) acc[i][j] = 0.f;

    const float4* A4 = (const float4*)A;
    const float4* W4 = (const float4*)W;
    int K4 = K >> 2;
    int ra = tid >> 2;          // 0..63
    int c4 = tid & 3;           // float4 within 16-float k-slab
    int nk = K >> 4;

    // prefetch tile 0
    float4 pa0 = A4[(size_t)(bm + ra)      * K4 + c4];
    float4 pa1 = A4[(size_t)(bm + ra + 64) * K4 + c4];
    float4 pb0 = W4[(size_t)(bn + ra)      * K4 + c4];

    for (int kt = 0; kt < nk; kt++) {
        __syncthreads();
        int cc = c4 * 4;
        As[cc + 0][ra] = pa0.x; As[cc + 1][ra] = pa0.y;
        As[cc + 2][ra] = pa0.z; As[cc + 3][ra] = pa0.w;
        As[cc + 0][ra + 64] = pa1.x; As[cc + 1][ra + 64] = pa1.y;
        As[cc + 2][ra + 64] = pa1.z; As[cc + 3][ra + 64] = pa1.w;
        Bs[cc + 0][ra] = pb0.x; Bs[cc + 1][ra] = pb0.y;
        Bs[cc + 2][ra] = pb0.z; Bs[cc + 3][ra] = pb0.w;
        __syncthreads();

        if (kt + 1 < nk) {
            int ko = (kt + 1) * 4;
            pa0 = A4[(size_t)(bm + ra)      * K4 + ko + c4];
            pa1 = A4[(size_t)(bm + ra + 64) * K4 + ko + c4];
            pb0 = W4[(size_t)(bn + ra)      * K4 + ko + c4];
        }

        #pragma unroll
        for (int k = 0; k < BK; k++) {
            float4 a01 = *(const float4*)&As[k][ty * 8];
            float4 a23 = *(const float4*)&As[k][ty * 8 + 4];
            float4 bq  = *(const float4*)&Bs[k][tx * 4];
            float av[8] = {a01.x, a01.y, a01.z, a01.w, a23.x, a23.y, a23.z, a23.w};
            float bv[4] = {bq.x, bq.y, bq.z, bq.w};
            #pragma unroll
            for (int i = 0; i < 8; i++)
                #pragma unroll
                for (int j = 0; j < 4; j++)
                    acc[i][j] += av[i] * bv[j];
        }
    }

    float4 b4 = *(const float4*)&bias[bn + tx * 4];
    float bvv[4] = {b4.x, b4.y, b4.z, b4.w};
    #pragma unroll
    for (int i = 0; i < 8; i++) {
        int row = bm + ty * 8 + i;
        float4 o;
        float v0 = acc[i][0] + bvv[0];
        float v1 = acc[i][1] + bvv[1];
        float v2 = acc[i][2] + bvv[2];
        float v3 = acc[i][3] + bvv[3];
        if (RELU) {
            v0 = fmaxf(v0, 0.f); v1 = fmaxf(v1, 0.f);
            v2 = fmaxf(v2, 0.f); v3 = fmaxf(v3, 0.f);
        }
        o.x = v0; o.y = v1; o.z = v2; o.w = v3;
        *(float4*)&C[(size_t)row * N + bn + tx * 4] = o;
    }
}

// ---------------- kernel 3: GRU combine (gi from prefix table) -------------
// one block per row, 512 threads (one per hidden unit)
__global__ __launch_bounds__(512) void k_gru(const float* __restrict__ bih)
{
    int row = blockIdx.x;
    int j = threadIdx.x;
    __shared__ int cnt[5];
    if (j < 5) cnt[j] = g_counts[row * 5 + j];
    __syncthreads();
    const float* p0 = g_pref + (0 * 20 + cnt[0]) * NGATE;
    const float* p1 = g_pref + (1 * 20 + cnt[1]) * NGATE;
    const float* p2 = g_pref + (2 * 20 + cnt[2]) * NGATE;
    const float* p3 = g_pref + (3 * 20 + cnt[3]) * NGATE;
    const float* p4 = g_pref + (4 * 20 + cnt[4]) * NGATE;

    float gir = bih[j]        + p0[j]        + p1[j]        + p2[j]        + p3[j]        + p4[j];
    float giz = bih[j + 512]  + p0[j + 512]  + p1[j + 512]  + p2[j + 512]  + p3[j + 512]  + p4[j + 512];
    float gin = bih[j + 1024] + p0[j + 1024] + p1[j + 1024] + p2[j + 1024] + p3[j + 1024] + p4[j + 1024];

    const float* gh = g_gh + (size_t)row * NGATE;
    float hr = gh[j], hz = gh[j + 512], hn = gh[j + 1024];

    float r = 1.f / (1.f + expf(-(gir + hr)));
    float z = 1.f / (1.f + expf(-(giz + hz)));
    float n = tanhf(gin + r * hn);
    float hp = g_bufA[(size_t)row * G_N + j];
    g_bufB[(size_t)row * G_N + j] = (1.f - z) * n + z * hp;
}

// ---------------- kernel 4: layernorm + score dot (x in g_bufA) ------------
// warp per row
__global__ __launch_bounds__(256) void k_lnscore(
    const float* __restrict__ lng, const float* __restrict__ lnb,
    const float* __restrict__ Ws, const float* __restrict__ bsc)
{
    int warp = threadIdx.x >> 5, lane = threadIdx.x & 31;
    int row = blockIdx.x * 8 + warp;
    const float* x = g_bufA + (size_t)row * D_N;
    float v[16];
    float sum = 0.f, sq = 0.f;
    #pragma unroll
    for (int i = 0; i < 16; i++) {
        v[i] = x[lane + 32 * i];
        sum += v[i]; sq += v[i] * v[i];
    }
    #pragma unroll
    for (int o = 16; o; o >>= 1) {
        sum += __shfl_xor_sync(0xffffffffu, sum, o);
        sq  += __shfl_xor_sync(0xffffffffu, sq,  o);
    }
    float mean = sum * (1.0f / D_N);
    float var  = sq  * (1.0f / D_N) - mean * mean;
    float inv  = rsqrtf(var + 1e-5f);
    float sc = 0.f;
    #pragma unroll
    for (int i = 0; i < 16; i++) {
        int c = lane + 32 * i;
        sc += ((v[i] - mean) * inv * lng[c] + lnb[c]) * Ws[c];
    }
    #pragma unroll
    for (int o = 16; o; o >>= 1) sc += __shfl_xor_sync(0xffffffffu, sc, o);
    if (lane == 0) g_scores[row] = sc + bsc[0];
}

// ---------------- kernel 5: softmax per batch -> probs in out[8192..] ------
__global__ __launch_bounds__(1024) void k_softmax(float* __restrict__ out)
{
    int b = blockIdx.x, tid = threadIdx.x;
    __shared__ float red[32];
    __shared__ float red2[32];
    float v[4];
    #pragma unroll
    for (int i = 0; i < 4; i++) v[i] = g_scores[b * S_N + tid + 1024 * i];
    float mx = fmaxf(fmaxf(v[0], v[1]), fmaxf(v[2], v[3]));
    #pragma unroll
    for (int o = 16; o; o >>= 1) mx = fmaxf(mx, __shfl_xor_sync(0xffffffffu, mx, o));
    if ((tid & 31) == 0) red[tid >> 5] = mx;
    __syncthreads();
    if (tid < 32) {
        float m2 = red[tid];
        #pragma unroll
        for (int o = 16; o; o >>= 1) m2 = fmaxf(m2, __shfl_xor_sync(0xffffffffu, m2, o));
        red[tid] = m2;
    }
    __syncthreads();
    mx = red[0];
    float s = 0.f;
    #pragma unroll
    for (int i = 0; i < 4; i++) { v[i] = expf(v[i] - mx); s += v[i]; }
    #pragma unroll
    for (int o = 16; o; o >>= 1) s += __shfl_xor_sync(0xffffffffu, s, o);
    if ((tid & 31) == 0) red2[tid >> 5] = s;
    __syncthreads();
    if (tid < 32) {
        float s2 = red2[tid];
        #pragma unroll
        for (int o = 16; o; o >>= 1) s2 += __shfl_xor_sync(0xffffffffu, s2, o);
        red2[tid] = s2;
    }
    __syncthreads();
    float invs = 1.f / red2[0];
    #pragma unroll
    for (int i = 0; i < 4; i++)
        out[BSZ * SPECT + b * S_N + tid + 1024 * i] = v[i] * invs;
}

// ---------------- kernel 6: spectrum scatter -------------------------------
__global__ void k_scatter(const float* __restrict__ peaks, float* __restrict__ out)
{
    int id = blockIdx.x * blockDim.x + threadIdx.x;   // BS*M
    if (id >= BS * M_N) return;
    int rs = id / M_N;            // b*S + s
    int b = rs / S_N;
    float mass  = peaks[(size_t)id * 2];
    float inten = peaks[(size_t)id * 2 + 1];
    int bin = (int)rintf(mass);   // round-half-even, matches jnp.round
    bin = bin < 0 ? 0 : (bin > SPECT - 1 ? SPECT - 1 : bin);
    float p = out[BSZ * SPECT + rs];
    atomicAdd(&out[b * SPECT + bin], inten * p);
}

// ---------------- launch ---------------------------------------------------
extern "C" void kernel_launch(void* const* d_in, const int* in_sizes, int n_in,
                              void* d_out, int out_size)
{
    const float* vf      = (const float*)d_in[0];
    const float* mask    = (const float*)d_in[1];
    const float* eo      = (const float*)d_in[2];
    // d_in[3] = adj_oh (unused by forward)
    const float* subsets = (const float*)d_in[4];
    const float* peaks   = (const float*)d_in[5];
    const float* lnsub_g = (const float*)d_in[6];
    const float* lnsub_b = (const float*)d_in[7];
    const float* W_ih    = (const float*)d_in[8];
    const float* W_hh    = (const float*)d_in[9];
    const float* b_ih    = (const float*)d_in[10];
    const float* b_hh    = (const float*)d_in[11];
    const float* W1      = (const float*)d_in[12];
    const float* b1      = (const float*)d_in[13];
    const float* W2a     = (const float*)d_in[14];
    const float* b2a     = (const float*)d_in[15];
    const float* W2b     = (const float*)d_in[16];
    const float* b2b     = (const float*)d_in[17];
    const float* lnpre_g = (const float*)d_in[18];
    const float* lnpre_b = (const float*)d_in[19];
    const float* Ws      = (const float*)d_in[20];
    const float* bsc     = (const float*)d_in[21];
    float* out = (float*)d_out;

    float *pA, *pB, *pGH;
    cudaGetSymbolAddress((void**)&pA,  g_bufA);
    cudaGetSymbolAddress((void**)&pB,  g_bufB);
    cudaGetSymbolAddress((void**)&pGH, g_gh);

    // zero the spectrum region of the output
    cudaMemsetAsync(d_out, 0, BSZ * SPECT * sizeof(float), 0);

    // 0) W_ih prefix table
    k_prefix<<<6, 256>>>(W_ih);

    // 1) swvs + counts + layernorm -> normed in g_bufA
    cudaFuncSetAttribute(k_pre, cudaFuncAttributeMaxDynamicSharedMemorySize, 65536);
    k_pre<<<dim3(64, 16), 256, 65536>>>(vf, mask, eo, subsets, lnsub_g, lnsub_b);

    // 2) gh = normed @ W_hh^T + b_hh
    k_gemm<false><<<dim3(NGATE / BN, BS / BM), 256>>>(pA, W_hh, b_hh, pGH, BS, NGATE, G_N);

    // 3) GRU combine -> h in g_bufB
    k_gru<<<BS, 512>>>(b_ih);

    // 4) MLP: h -> x1 (A) -> x2 (B) -> x3 (A)
    k_gemm<true><<<dim3(D_N / BN, BS / BM), 256>>>(pB, W1,  b1,  pA, BS, D_N, G_N);
    k_gemm<true><<<dim3(D_N / BN, BS / BM), 256>>>(pA, W2a, b2a, pB, BS, D_N, D_N);
    k_gemm<true><<<dim3(D_N / BN, BS / BM), 256>>>(pB, W2b, b2b, pA, BS, D_N, D_N);

    // 5) layernorm + score
    k_lnscore<<<BS / 8, 256>>>(lnpre_g, lnpre_b, Ws, bsc);

    // 6) softmax -> probs (out[8192..]); 7) scatter -> spect (out[0..8191])
    k_softmax<<<BSZ, 1024>>>(out);
    k_scatter<<<(BS * M_N + 255) / 256, 256>>>(peaks, out);
}

// round 5
// speedup vs baseline: 1.9627x; 1.9627x over previous
#include <cuda_runtime.h>
#include <cuda_bf16.h>
#include <math.h>
#include <stdint.h>

// ---------------- problem constants ----------------
#define BSZ   16
#define A_N   32
#define G_N   512
#define S_N   4096
#define M_N   8
#define D_N   512
#define BS    (BSZ * S_N)      // 65536 rows
#define NGATE 1536
#define SPECT 512

// ---------------- scratch (device globals; no allocation allowed) ----------
__device__ float g_pref[5 * 20 * NGATE];
__device__ int   g_counts[BS * 5];
__device__ float g_gh[(size_t)BS * NGATE];       // gh fp32, reused as x3 fp32
__device__ float g_scores[BS];
__device__ __align__(16) __nv_bfloat16 g_ahi[(size_t)BS * G_N];
__device__ __align__(16) __nv_bfloat16 g_alo[(size_t)BS * G_N];
__device__ __align__(16) __nv_bfloat16 g_bhi[(size_t)BS * G_N];
__device__ __align__(16) __nv_bfloat16 g_blo[(size_t)BS * G_N];
__device__ __align__(16) __nv_bfloat16 g_whh_hi[NGATE * G_N], g_whh_lo[NGATE * G_N];
__device__ __align__(16) __nv_bfloat16 g_w1_hi[D_N * G_N],  g_w1_lo[D_N * G_N];
__device__ __align__(16) __nv_bfloat16 g_w2a_hi[D_N * G_N], g_w2a_lo[D_N * G_N];
__device__ __align__(16) __nv_bfloat16 g_w2b_hi[D_N * G_N], g_w2b_lo[D_N * G_N];

// ---------------- helpers ---------------------------------------------------
__device__ __forceinline__ uint32_t smem_u32(const void* p) {
    uint32_t a;
    asm("{ .reg .u64 t; cvta.to.shared.u64 t, %1; cvt.u32.u64 %0, t; }" : "=r"(a) : "l"(p));
    return a;
}
__device__ __forceinline__ void ldsm4(uint32_t r[4], uint32_t addr) {
    asm volatile("ldmatrix.sync.aligned.m8n8.x4.shared.b16 {%0,%1,%2,%3}, [%4];"
        : "=r"(r[0]), "=r"(r[1]), "=r"(r[2]), "=r"(r[3]) : "r"(addr));
}
__device__ __forceinline__ void mma_bf16(float c[4], const uint32_t a[4], const uint32_t b[2]) {
    asm volatile("mma.sync.aligned.m16n8k16.row.col.f32.bf16.bf16.f32 "
        "{%0,%1,%2,%3}, {%4,%5,%6,%7}, {%8,%9}, {%0,%1,%2,%3};"
        : "+f"(c[0]), "+f"(c[1]), "+f"(c[2]), "+f"(c[3])
        : "r"(a[0]), "r"(a[1]), "r"(a[2]), "r"(a[3]), "r"(b[0]), "r"(b[1]));
}
#define CP16(dst, src) asm volatile("cp.async.cg.shared.global [%0], [%1], 16;" :: "r"(dst), "l"(src))
#define CPCOMMIT()     asm volatile("cp.async.commit_group;" ::: "memory")
__device__ __forceinline__ void cp_wait1() { asm volatile("cp.async.wait_group 1;" ::: "memory"); }
__device__ __forceinline__ void cp_wait0() { asm volatile("cp.async.wait_group 0;" ::: "memory"); }

// ---------------- kernel 0: prefix-sum W_ih columns ------------------------
__global__ void k_prefix(const float* __restrict__ W_ih) {
    int o = blockIdx.x * blockDim.x + threadIdx.x;
    if (o >= NGATE) return;
    #pragma unroll
    for (int g = 0; g < 5; g++) {
        float acc = 0.f;
        #pragma unroll
        for (int j = 0; j < 20; j++) {
            acc += W_ih[o * 100 + g * 20 + j];
            g_pref[(g * 20 + j) * NGATE + o] = acc;
        }
    }
}

// ---------------- weight hi/lo split ---------------------------------------
__global__ void k_split(const float* __restrict__ W, __nv_bfloat16* __restrict__ hi,
                        __nv_bfloat16* __restrict__ lo, int n) {
    int i = blockIdx.x * 256 + threadIdx.x;
    if (i >= n) return;
    float w = W[i];
    __nv_bfloat16 h = __float2bfloat16(w);
    hi[i] = h;
    lo[i] = __float2bfloat16(w - __bfloat162float(h));
}

// ---------------- kernel 1: swvs + counts + layernorm -> hi/lo -------------
__global__ __launch_bounds__(256) void k_pre(
    const float* __restrict__ vf, const float* __restrict__ mask,
    const float* __restrict__ eo, const float* __restrict__ subsets,
    const float* __restrict__ lng, const float* __restrict__ lnb)
{
    extern __shared__ float vfs[];
    __shared__ float s_lng[G_N], s_lnb[G_N];
    int b = blockIdx.y;
    int chunk = blockIdx.x;
    int tid = threadIdx.x;

    const float4* vf4 = (const float4*)(vf + (size_t)b * A_N * G_N);
    float4* vfs4 = (float4*)vfs;
    for (int i = tid; i < A_N * G_N / 4; i += 256) {
        float4 v = vf4[i];
        float m = mask[b * A_N + (i * 4) / G_N];
        v.x *= m; v.y *= m; v.z *= m; v.w *= m;
        vfs4[i] = v;
    }
    for (int i = tid; i < G_N; i += 256) { s_lng[i] = lng[i]; s_lnb[i] = lnb[i]; }
    __syncthreads();

    int warp = tid >> 5, lane = tid & 31;
    for (int it = 0; it < 8; it++) {
        int s = chunk * 64 + it * 8 + warp;
        int row = b * S_N + s;
        float as = subsets[(size_t)row * A_N + lane];
        float m  = mask[b * A_N + lane];
        float sm = as * m;

        float ss = sm;
        #pragma unroll
        for (int o = 16; o; o >>= 1) ss += __shfl_xor_sync(0xffffffffu, ss, o);

        #pragma unroll
        for (int e = 0; e < 5; e++) {
            float c = as * eo[(b * A_N + lane) * 5 + e];
            #pragma unroll
            for (int o = 16; o; o >>= 1) c += __shfl_xor_sync(0xffffffffu, c, o);
            if (lane == e) {
                int v = (int)c;
                v = v < 0 ? 0 : (v > 19 ? 19 : v);
                g_counts[row * 5 + e] = v;
            }
        }

        float inv_ss = 1.0f / (ss + 1e-4f);

        float acc[16];
        #pragma unroll
        for (int i = 0; i < 16; i++) acc[i] = 0.f;
        #pragma unroll
        for (int a = 0; a < A_N; a++) {
            float sv = __shfl_sync(0xffffffffu, sm, a);
            #pragma unroll
            for (int i = 0; i < 16; i++)
                acc[i] += vfs[a * G_N + lane + 32 * i] * sv;
        }

        float sum = 0.f, sq = 0.f;
        #pragma unroll
        for (int i = 0; i < 16; i++) {
            acc[i] *= inv_ss;
            sum += acc[i];
            sq  += acc[i] * acc[i];
        }
        #pragma unroll
        for (int o = 16; o; o >>= 1) {
            sum += __shfl_xor_sync(0xffffffffu, sum, o);
            sq  += __shfl_xor_sync(0xffffffffu, sq,  o);
        }
        float mean = sum * (1.0f / G_N);
        float var  = sq  * (1.0f / G_N) - mean * mean;
        float inv  = rsqrtf(var + 1e-5f);
        #pragma unroll
        for (int i = 0; i < 16; i++) {
            int gc = lane + 32 * i;
            float v = (acc[i] - mean) * inv * s_lng[gc] + s_lnb[gc];
            __nv_bfloat16 h = __float2bfloat16(v);
            g_ahi[(size_t)row * G_N + gc] = h;
            g_alo[(size_t)row * G_N + gc] = __float2bfloat16(v - __bfloat162float(h));
        }
    }
}

// ---------------- mma.sync GEMM: C = epi(A @ W^T + bias) -------------------
// A: [M,512] bf16 hi/lo row-major; W: [NTOT,512] bf16 hi/lo row-major.
// CTA tile 128x128, 8 warps (4m x 2n), warp tile 32x64.
// K chunks of 32, double-buffered cp.async. smem rows padded to 40 bf16 (80B).
// Both A and W are K-contiguous -> NON-trans ldmatrix for both (B fragment
// wants lane l = W[n=l/4][k=2(l%4)+j], i.e. consecutive-k pairs).
// EPI: 0 = fp32+bias; 1 = relu -> bf16 hi/lo; 2 = relu -> fp32.
#define STRIDE_E 40
#define TB (128 * STRIDE_E * 2)          // 10240 B per tile
#define SMEM_DYN (8 * TB)                // 2 stages x 4 tiles = 80 KB

template<int NTOT, int EPI>
__global__ __launch_bounds__(256, 2) void k_mgemm(
    const __nv_bfloat16* __restrict__ Ahi, const __nv_bfloat16* __restrict__ Alo,
    const __nv_bfloat16* __restrict__ Whi, const __nv_bfloat16* __restrict__ Wlo,
    const float* __restrict__ bias,
    float* __restrict__ Cf, __nv_bfloat16* __restrict__ Chi, __nv_bfloat16* __restrict__ Clo)
{
    extern __shared__ char dsm[];
    const int tid = threadIdx.x, lane = tid & 31, wid = tid >> 5;
    const int wm = wid & 3, wn = wid >> 2;
    const int bm = blockIdx.y * 128, bn = blockIdx.x * 128;
    const uint32_t sbase = smem_u32(dsm);

    const __nv_bfloat16* srcs[4] = {
        Ahi + (size_t)bm * G_N, Alo + (size_t)bm * G_N,
        Whi + (size_t)bn * G_N, Wlo + (size_t)bn * G_N };

    float c[2][8][4];
    #pragma unroll
    for (int i = 0; i < 2; i++)
        #pragma unroll
        for (int j = 0; j < 8; j++)
            #pragma unroll
            for (int q = 0; q < 4; q++) c[i][j][q] = 0.f;

    const int row_l = tid >> 2;       // 0..63 (two rows per thread via +64)
    const int c16   = tid & 3;

    // ---- prologue: chunk 0 into stage 0
    #pragma unroll
    for (int t = 0; t < 4; t++) {
        uint32_t sd = sbase + t * TB;
        CP16(sd + row_l * 80 + c16 * 16,
             srcs[t] + (size_t)row_l * G_N + c16 * 8);
        CP16(sd + (row_l + 64) * 80 + c16 * 16,
             srcs[t] + (size_t)(row_l + 64) * G_N + c16 * 8);
    }
    CPCOMMIT();

    // ldmatrix lane addressing (element offsets within tile)
    // A: groups {m0-7/k0, m8-15/k0, m0-7/k8, m8-15/k8}
    const int a_row = wm * 32 + (lane & 7) + ((lane >> 3) & 1) * 8;
    const int a_kad = (lane >> 4) * 8;
    // W (non-trans B): groups {n0-7/k0, n0-7/k8, n8-15/k0, n8-15/k8}
    const int w_row = wn * 64 + (lane & 7) + ((lane >> 4) & 1) * 8;
    const int w_kad = ((lane >> 3) & 1) * 8;

    #pragma unroll 1
    for (int kc = 0; kc < 16; kc++) {
        const int s = kc & 1;
        if (kc + 1 < 16) {
            const int ns = (kc + 1) & 1;
            const int kcol = (kc + 1) * 32;
            #pragma unroll
            for (int t = 0; t < 4; t++) {
                uint32_t sd = sbase + (ns * 4 + t) * TB;
                CP16(sd + row_l * 80 + c16 * 16,
                     srcs[t] + (size_t)row_l * G_N + kcol + c16 * 8);
                CP16(sd + (row_l + 64) * 80 + c16 * 16,
                     srcs[t] + (size_t)(row_l + 64) * G_N + kcol + c16 * 8);
            }
            CPCOMMIT();
            cp_wait1();
        } else {
            cp_wait0();
        }
        __syncthreads();

        const uint32_t tA = sbase + (s * 4) * TB;
        const uint32_t tW = sbase + (s * 4 + 2) * TB;
        #pragma unroll
        for (int ks = 0; ks < 2; ks++) {
            uint32_t ah[2][4], al[2][4];
            #pragma unroll
            for (int mt = 0; mt < 2; mt++) {
                uint32_t ad = tA + ((a_row + mt * 16) * STRIDE_E + a_kad + ks * 16) * 2;
                ldsm4(ah[mt], ad);
                ldsm4(al[mt], ad + TB);
            }
            #pragma unroll
            for (int np = 0; np < 4; np++) {
                uint32_t bd = tW + ((w_row + np * 16) * STRIDE_E + w_kad + ks * 16) * 2;
                uint32_t bh[4], bl[4];
                ldsm4(bh, bd);           // FIX: non-trans (W is K-contiguous)
                ldsm4(bl, bd + TB);      // FIX: non-trans
                #pragma unroll
                for (int p = 0; p < 2; p++) {
                    const int nt = np * 2 + p;
                    mma_bf16(c[0][nt], ah[0], &bh[p * 2]);
                    mma_bf16(c[1][nt], ah[1], &bh[p * 2]);
                    mma_bf16(c[0][nt], ah[0], &bl[p * 2]);
                    mma_bf16(c[1][nt], ah[1], &bl[p * 2]);
                    mma_bf16(c[0][nt], al[0], &bh[p * 2]);
                    mma_bf16(c[1][nt], al[1], &bh[p * 2]);
                }
            }
        }
        __syncthreads();
    }

    // ---- epilogue
    const int r_base = bm + wm * 32 + (lane >> 2);
    const int c_base = bn + wn * 64 + (lane & 3) * 2;
    #pragma unroll
    for (int mt = 0; mt < 2; mt++) {
        #pragma unroll
        for (int nt = 0; nt < 8; nt++) {
            const int row0 = r_base + mt * 16;
            const int row1 = row0 + 8;
            const int col  = c_base + nt * 8;
            const float b0 = bias[col], b1 = bias[col + 1];
            float v00 = c[mt][nt][0] + b0, v01 = c[mt][nt][1] + b1;
            float v10 = c[mt][nt][2] + b0, v11 = c[mt][nt][3] + b1;
            if (EPI == 1) {
                v00 = fmaxf(v00, 0.f); v01 = fmaxf(v01, 0.f);
                v10 = fmaxf(v10, 0.f); v11 = fmaxf(v11, 0.f);
                __nv_bfloat16 h00 = __float2bfloat16(v00), h01 = __float2bfloat16(v01);
                __nv_bfloat16 h10 = __float2bfloat16(v10), h11 = __float2bfloat16(v11);
                __nv_bfloat162 hp0; hp0.x = h00; hp0.y = h01;
                __nv_bfloat162 hp1; hp1.x = h10; hp1.y = h11;
                *(__nv_bfloat162*)&Chi[(size_t)row0 * NTOT + col] = hp0;
                *(__nv_bfloat162*)&Chi[(size_t)row1 * NTOT + col] = hp1;
                __nv_bfloat162 lp0, lp1;
                lp0.x = __float2bfloat16(v00 - __bfloat162float(h00));
                lp0.y = __float2bfloat16(v01 - __bfloat162float(h01));
                lp1.x = __float2bfloat16(v10 - __bfloat162float(h10));
                lp1.y = __float2bfloat16(v11 - __bfloat162float(h11));
                *(__nv_bfloat162*)&Clo[(size_t)row0 * NTOT + col] = lp0;
                *(__nv_bfloat162*)&Clo[(size_t)row1 * NTOT + col] = lp1;
            } else {
                if (EPI == 2) {
                    v00 = fmaxf(v00, 0.f); v01 = fmaxf(v01, 0.f);
                    v10 = fmaxf(v10, 0.f); v11 = fmaxf(v11, 0.f);
                }
                float2 o0; o0.x = v00; o0.y = v01;
                float2 o1; o1.x = v10; o1.y = v11;
                *(float2*)&Cf[(size_t)row0 * NTOT + col] = o0;
                *(float2*)&Cf[(size_t)row1 * NTOT + col] = o1;
            }
        }
    }
}

// ---------------- GRU combine ----------------------------------------------
__global__ __launch_bounds__(512) void k_gru(const float* __restrict__ bih)
{
    int row = blockIdx.x;
    int j = threadIdx.x;
    __shared__ int cnt[5];
    if (j < 5) cnt[j] = g_counts[row * 5 + j];
    __syncthreads();
    const float* p0 = g_pref + (0 * 20 + cnt[0]) * NGATE;
    const float* p1 = g_pref + (1 * 20 + cnt[1]) * NGATE;
    const float* p2 = g_pref + (2 * 20 + cnt[2]) * NGATE;
    const float* p3 = g_pref + (3 * 20 + cnt[3]) * NGATE;
    const float* p4 = g_pref + (4 * 20 + cnt[4]) * NGATE;

    float gir = bih[j]        + p0[j]        + p1[j]        + p2[j]        + p3[j]        + p4[j];
    float giz = bih[j + 512]  + p0[j + 512]  + p1[j + 512]  + p2[j + 512]  + p3[j + 512]  + p4[j + 512];
    float gin = bih[j + 1024] + p0[j + 1024] + p1[j + 1024] + p2[j + 1024] + p3[j + 1024] + p4[j + 1024];

    const float* gh = g_gh + (size_t)row * NGATE;
    float hr = gh[j], hz = gh[j + 512], hn = gh[j + 1024];

    float r = 1.f / (1.f + expf(-(gir + hr)));
    float z = 1.f / (1.f + expf(-(giz + hz)));
    float n = tanhf(gin + r * hn);
    size_t idx = (size_t)row * G_N + j;
    float hp = __bfloat162float(g_ahi[idx]) + __bfloat162float(g_alo[idx]);
    float h = (1.f - z) * n + z * hp;
    __nv_bfloat16 hh = __float2bfloat16(h);
    g_bhi[idx] = hh;
    g_blo[idx] = __float2bfloat16(h - __bfloat162float(hh));
}

// ---------------- layernorm + score ----------------------------------------
__global__ __launch_bounds__(256) void k_lnscore(
    const float* __restrict__ x3,
    const float* __restrict__ lng, const float* __restrict__ lnb,
    const float* __restrict__ Ws, const float* __restrict__ bsc)
{
    int warp = threadIdx.x >> 5, lane = threadIdx.x & 31;
    int row = blockIdx.x * 8 + warp;
    const float* x = x3 + (size_t)row * D_N;
    float v[16];
    float sum = 0.f, sq = 0.f;
    #pragma unroll
    for (int i = 0; i < 16; i++) {
        v[i] = x[lane + 32 * i];
        sum += v[i]; sq += v[i] * v[i];
    }
    #pragma unroll
    for (int o = 16; o; o >>= 1) {
        sum += __shfl_xor_sync(0xffffffffu, sum, o);
        sq  += __shfl_xor_sync(0xffffffffu, sq,  o);
    }
    float mean = sum * (1.0f / D_N);
    float var  = sq  * (1.0f / D_N) - mean * mean;
    float inv  = rsqrtf(var + 1e-5f);
    float sc = 0.f;
    #pragma unroll
    for (int i = 0; i < 16; i++) {
        int cc = lane + 32 * i;
        sc += ((v[i] - mean) * inv * lng[cc] + lnb[cc]) * Ws[cc];
    }
    #pragma unroll
    for (int o = 16; o; o >>= 1) sc += __shfl_xor_sync(0xffffffffu, sc, o);
    if (lane == 0) g_scores[row] = sc + bsc[0];
}

// ---------------- softmax ---------------------------------------------------
__global__ __launch_bounds__(1024) void k_softmax(float* __restrict__ out)
{
    int b = blockIdx.x, tid = threadIdx.x;
    __shared__ float red[32];
    __shared__ float red2[32];
    float v[4];
    #pragma unroll
    for (int i = 0; i < 4; i++) v[i] = g_scores[b * S_N + tid + 1024 * i];
    float mx = fmaxf(fmaxf(v[0], v[1]), fmaxf(v[2], v[3]));
    #pragma unroll
    for (int o = 16; o; o >>= 1) mx = fmaxf(mx, __shfl_xor_sync(0xffffffffu, mx, o));
    if ((tid & 31) == 0) red[tid >> 5] = mx;
    __syncthreads();
    if (tid < 32) {
        float m2 = red[tid];
        #pragma unroll
        for (int o = 16; o; o >>= 1) m2 = fmaxf(m2, __shfl_xor_sync(0xffffffffu, m2, o));
        red[tid] = m2;
    }
    __syncthreads();
    mx = red[0];
    float s = 0.f;
    #pragma unroll
    for (int i = 0; i < 4; i++) { v[i] = expf(v[i] - mx); s += v[i]; }
    #pragma unroll
    for (int o = 16; o; o >>= 1) s += __shfl_xor_sync(0xffffffffu, s, o);
    if ((tid & 31) == 0) red2[tid >> 5] = s;
    __syncthreads();
    if (tid < 32) {
        float s2 = red2[tid];
        #pragma unroll
        for (int o = 16; o; o >>= 1) s2 += __shfl_xor_sync(0xffffffffu, s2, o);
        red2[tid] = s2;
    }
    __syncthreads();
    float invs = 1.f / red2[0];
    #pragma unroll
    for (int i = 0; i < 4; i++)
        out[BSZ * SPECT + b * S_N + tid + 1024 * i] = v[i] * invs;
}

// ---------------- scatter ---------------------------------------------------
__global__ void k_scatter(const float* __restrict__ peaks, float* __restrict__ out)
{
    int id = blockIdx.x * blockDim.x + threadIdx.x;
    if (id >= BS * M_N) return;
    int rs = id / M_N;
    int b = rs / S_N;
    float mass  = peaks[(size_t)id * 2];
    float inten = peaks[(size_t)id * 2 + 1];
    int bin = (int)rintf(mass);
    bin = bin < 0 ? 0 : (bin > SPECT - 1 ? SPECT - 1 : bin);
    float p = out[BSZ * SPECT + rs];
    atomicAdd(&out[b * SPECT + bin], inten * p);
}

// ---------------- launch ---------------------------------------------------
extern "C" void kernel_launch(void* const* d_in, const int* in_sizes, int n_in,
                              void* d_out, int out_size)
{
    const float* vf      = (const float*)d_in[0];
    const float* mask    = (const float*)d_in[1];
    const float* eo      = (const float*)d_in[2];
    const float* subsets = (const float*)d_in[4];
    const float* peaks   = (const float*)d_in[5];
    const float* lnsub_g = (const float*)d_in[6];
    const float* lnsub_b = (const float*)d_in[7];
    const float* W_ih    = (const float*)d_in[8];
    const float* W_hh    = (const float*)d_in[9];
    const float* b_ih    = (const float*)d_in[10];
    const float* b_hh    = (const float*)d_in[11];
    const float* W1      = (const float*)d_in[12];
    const float* b1      = (const float*)d_in[13];
    const float* W2a     = (const float*)d_in[14];
    const float* b2a     = (const float*)d_in[15];
    const float* W2b     = (const float*)d_in[16];
    const float* b2b     = (const float*)d_in[17];
    const float* lnpre_g = (const float*)d_in[18];
    const float* lnpre_b = (const float*)d_in[19];
    const float* Ws      = (const float*)d_in[20];
    const float* bsc     = (const float*)d_in[21];
    float* out = (float*)d_out;

    __nv_bfloat16 *ahi, *alo, *bhi, *blo;
    __nv_bfloat16 *whh_hi, *whh_lo, *w1_hi, *w1_lo, *w2a_hi, *w2a_lo, *w2b_hi, *w2b_lo;
    float* pGH;
    cudaGetSymbolAddress((void**)&ahi, g_ahi);
    cudaGetSymbolAddress((void**)&alo, g_alo);
    cudaGetSymbolAddress((void**)&bhi, g_bhi);
    cudaGetSymbolAddress((void**)&blo, g_blo);
    cudaGetSymbolAddress((void**)&whh_hi, g_whh_hi);
    cudaGetSymbolAddress((void**)&whh_lo, g_whh_lo);
    cudaGetSymbolAddress((void**)&w1_hi, g_w1_hi);
    cudaGetSymbolAddress((void**)&w1_lo, g_w1_lo);
    cudaGetSymbolAddress((void**)&w2a_hi, g_w2a_hi);
    cudaGetSymbolAddress((void**)&w2a_lo, g_w2a_lo);
    cudaGetSymbolAddress((void**)&w2b_hi, g_w2b_hi);
    cudaGetSymbolAddress((void**)&w2b_lo, g_w2b_lo);
    cudaGetSymbolAddress((void**)&pGH, g_gh);

    cudaMemsetAsync(d_out, 0, BSZ * SPECT * sizeof(float), 0);

    k_prefix<<<6, 256>>>(W_ih);
    k_split<<<(NGATE * G_N + 255) / 256, 256>>>(W_hh, whh_hi, whh_lo, NGATE * G_N);
    k_split<<<(D_N * G_N + 255) / 256, 256>>>(W1,  w1_hi,  w1_lo,  D_N * G_N);
    k_split<<<(D_N * G_N + 255) / 256, 256>>>(W2a, w2a_hi, w2a_lo, D_N * G_N);
    k_split<<<(D_N * G_N + 255) / 256, 256>>>(W2b, w2b_hi, w2b_lo, D_N * G_N);

    cudaFuncSetAttribute(k_pre, cudaFuncAttributeMaxDynamicSharedMemorySize, 65536);
    k_pre<<<dim3(64, 16), 256, 65536>>>(vf, mask, eo, subsets, lnsub_g, lnsub_b);

    cudaFuncSetAttribute(k_mgemm<1536, 0>, cudaFuncAttributeMaxDynamicSharedMemorySize, SMEM_DYN);
    cudaFuncSetAttribute(k_mgemm<512, 1>,  cudaFuncAttributeMaxDynamicSharedMemorySize, SMEM_DYN);
    cudaFuncSetAttribute(k_mgemm<512, 2>,  cudaFuncAttributeMaxDynamicSharedMemorySize, SMEM_DYN);

    // gh = normed @ W_hh^T + b_hh  (fp32 out)
    k_mgemm<1536, 0><<<dim3(12, 512), 256, SMEM_DYN>>>(
        ahi, alo, whh_hi, whh_lo, b_hh, pGH, nullptr, nullptr);

    // GRU combine -> h (bf16 hi/lo)
    k_gru<<<BS, 512>>>(b_ih);

    // MLP
    k_mgemm<512, 1><<<dim3(4, 512), 256, SMEM_DYN>>>(
        bhi, blo, w1_hi, w1_lo, b1, nullptr, ahi, alo);
    k_mgemm<512, 1><<<dim3(4, 512), 256, SMEM_DYN>>>(
        ahi, alo, w2a_hi, w2a_lo, b2a, nullptr, bhi, blo);
    k_mgemm<512, 2><<<dim3(4, 512), 256, SMEM_DYN>>>(
        bhi, blo, w2b_hi, w2b_lo, b2b, pGH, nullptr, nullptr);

    k_lnscore<<<BS / 8, 256>>>(pGH, lnpre_g, lnpre_b, Ws, bsc);
    k_softmax<<<BSZ, 1024>>>(out);
    k_scatter<<<(BS * M_N + 255) / 256, 256>>>(peaks, out);
}